// round 14
// baseline (speedup 1.0000x reference)
#include <cuda_runtime.h>

#define NB     256
#define NSETS  1000
#define NGENES 10000
#define GG     128
#define H1V    64
#define H2V    32
#define EPSV   1e-5f

// Padded row length for SMEM transpose buffers (bank-conflict-free stats reads)
#define ROWP   260

// Scratch for transposed x: xT[gene][batch], 10000 x 256 floats = 10.24 MB
__device__ float g_xT[(size_t)NGENES * NB];

typedef unsigned long long ull;

__device__ __forceinline__ ull pack2(float lo, float hi) {
    ull r;
    asm("mov.b64 %0, {%1, %2};" : "=l"(r) : "f"(lo), "f"(hi));
    return r;
}
__device__ __forceinline__ void unpack2(ull v, float& lo, float& hi) {
    asm("mov.b64 {%0, %1}, %2;" : "=f"(lo), "=f"(hi) : "l"(v));
}
// Packed dual-fp32 FMA: d = a*b + d  (elementwise on the two 32-bit halves)
__device__ __forceinline__ void ffma2(ull& d, ull a, ull b) {
    asm("fma.rn.f32x2 %0, %1, %2, %0;" : "+l"(d) : "l"(a), "l"(b));
}

// ---------------------------------------------------------------------------
// Kernel 1: transpose x [256, 10000] -> g_xT [10000, 256]
// so the per-set gene gather becomes a coalesced contiguous row read.
// ---------------------------------------------------------------------------
__global__ void transpose_kernel(const float* __restrict__ x) {
    __shared__ float tile[32][33];
    int tx = threadIdx.x, ty = threadIdx.y;
    int c0 = blockIdx.x * 32;      // gene dim
    int r0 = blockIdx.y * 32;      // batch dim (256 = 8*32, exact)

    #pragma unroll
    for (int i = 0; i < 32; i += 8) {
        int c = c0 + tx;
        if (c < NGENES)
            tile[ty + i][tx] = x[(size_t)(r0 + ty + i) * NGENES + c];
    }
    __syncthreads();
    #pragma unroll
    for (int i = 0; i < 32; i += 8) {
        int gene = c0 + ty + i;
        if (gene < NGENES)
            g_xT[(size_t)gene * NB + r0 + tx] = tile[tx][ty + i];
    }
}

// ---------------------------------------------------------------------------
// Kernel 2: one CTA per set. 256 threads, thread t = batch row.
// SMEM layout (floats):
//   [0,      8320)  region A: w1s (first 8192 used) -> reused as h2buf (32*260)
//   [8320,  24960)  h1buf  (64*260)
//   [24960, 27008)  w2s    (64*32)
//   [27008, 27072)  b1s
//   [27072, 27136)  sc1
//   [27136, 27200)  sh1
//   [27200, 27232)  b2s
//   [27232, 27264)  sc2
//   [27264, 27296)  sh2
//   [27296, 27328)  w3s
//   [27328, 27840)  ps (partial reduction buffer, 512)
//   [27840, 27968)  idxs (128 ints)
// total 27968 floats = 111872 bytes
// ---------------------------------------------------------------------------
#define SMEM_FLOATS 27968
#define SMEM_BYTES  (SMEM_FLOATS * 4)

__global__ __launch_bounds__(256, 2)
void geneset_kernel(const int* __restrict__ gene_idx,
                    const float* __restrict__ W1, const float* __restrict__ b1,
                    const float* __restrict__ g1, const float* __restrict__ be1,
                    const float* __restrict__ W2, const float* __restrict__ b2,
                    const float* __restrict__ g2, const float* __restrict__ be2,
                    const float* __restrict__ W3, const float* __restrict__ b3,
                    float* __restrict__ out)
{
    extern __shared__ float sm[];
    float* w1s   = sm;            // 128*64, reused as h2buf after layer 1
    float* h2buf = sm;            // 32*260 (alias, safe: w1s dead after layer 1)
    float* h1buf = sm + 8320;     // 64*260
    float* w2s   = sm + 24960;    // 64*32
    float* b1s   = sm + 27008;
    float* sc1   = sm + 27072;
    float* sh1   = sm + 27136;
    float* b2s   = sm + 27200;
    float* sc2   = sm + 27232;
    float* sh2   = sm + 27264;
    float* w3s   = sm + 27296;
    float* ps    = sm + 27328;    // 512
    int*   idxs  = (int*)(sm + 27840);

    const int s = blockIdx.x;
    const int t = threadIdx.x;

    // ---- cooperative loads of per-set parameters ----
    {
        const float4* w1g = (const float4*)(W1 + (size_t)s * (GG * H1V));
        float4* dst = (float4*)w1s;
        #pragma unroll
        for (int i = 0; i < 8; i++) dst[t + 256 * i] = w1g[t + 256 * i];

        const float4* w2g = (const float4*)(W2 + (size_t)s * (H1V * H2V));
        float4* dst2 = (float4*)w2s;
        #pragma unroll
        for (int i = 0; i < 2; i++) dst2[t + 256 * i] = w2g[t + 256 * i];

        if (t < GG)  idxs[t] = gene_idx[s * GG + t];
        if (t < H1V) b1s[t] = b1[(size_t)s * H1V + t];
        if (t < H2V) { b2s[t] = b2[(size_t)s * H2V + t]; w3s[t] = W3[(size_t)s * H2V + t]; }
    }
    __syncthreads();

    // ---- layer 1: z1[t][h] = sum_g xT[idx[g]][t] * W1[g][h]  (h = 0..63) ----
    // acc[j] holds features (2j, 2j+1); 32 ull = 64 features.
    ull acc[32];
    #pragma unroll
    for (int i = 0; i < 32; i++) acc[i] = 0ull;

    #pragma unroll 1
    for (int g0 = 0; g0 < GG; g0 += 4) {
        float xv[4];
        #pragma unroll
        for (int u = 0; u < 4; u++)
            xv[u] = g_xT[(size_t)idxs[g0 + u] * NB + t];   // coalesced, L2-hot
        #pragma unroll
        for (int u = 0; u < 4; u++) {
            ull xp = pack2(xv[u], xv[u]);
            const ulonglong2* wr = (const ulonglong2*)(w1s + (g0 + u) * H1V);
            #pragma unroll
            for (int i = 0; i < 16; i++) {            // 16 x LDS.128 = 64 floats
                ulonglong2 w = wr[i];                 // features 4i..4i+3
                ffma2(acc[2 * i],     w.x, xp);
                ffma2(acc[2 * i + 1], w.y, xp);
            }
        }
    }

    // bias + relu, store transposed into h1buf for BN stats
    #pragma unroll
    for (int i = 0; i < 32; i++) {
        float lo, hi;
        unpack2(acc[i], lo, hi);
        lo = fmaxf(lo + b1s[2 * i],     0.0f);
        hi = fmaxf(hi + b1s[2 * i + 1], 0.0f);
        h1buf[(2 * i)     * ROWP + t] = lo;
        h1buf[(2 * i + 1) * ROWP + t] = hi;
    }
    __syncthreads();

    // ---- BN1 stats: 4 threads per feature, 64 elements each ----
    {
        int f = t >> 2, part = t & 3;
        const float4* hv = (const float4*)(h1buf + f * ROWP + part * 64);
        float sum = 0.0f, sq = 0.0f;
        #pragma unroll
        for (int i = 0; i < 16; i++) {
            float4 v = hv[i];
            sum += v.x + v.y + v.z + v.w;
            sq  += v.x * v.x + v.y * v.y + v.z * v.z + v.w * v.w;
        }
        ps[t] = sum;
        ps[256 + t] = sq;
    }
    __syncthreads();
    if (t < H1V) {
        float sum = ps[4 * t] + ps[4 * t + 1] + ps[4 * t + 2] + ps[4 * t + 3];
        float sq  = ps[256 + 4 * t] + ps[256 + 4 * t + 1] + ps[256 + 4 * t + 2] + ps[256 + 4 * t + 3];
        float mean = sum * (1.0f / NB);
        float var  = sq * (1.0f / NB) - mean * mean;
        float sc   = g1[(size_t)s * H1V + t] * rsqrtf(var + EPSV);
        sc1[t] = sc;
        sh1[t] = be1[(size_t)s * H1V + t] - mean * sc;
    }
    __syncthreads();

    // ---- layer 2: z2[t][k] = sum_h bn1(h1[t][h]) * W2[h][k]  (k = 0..31) ----
    // acc2[j] holds features (2j, 2j+1); 16 ull = 32 features.
    ull acc2[16];
    #pragma unroll
    for (int i = 0; i < 16; i++) acc2[i] = 0ull;

    #pragma unroll 2
    for (int h = 0; h < H1V; h++) {
        float hv = fmaf(h1buf[h * ROWP + t], sc1[h], sh1[h]);
        ull hp = pack2(hv, hv);
        const ulonglong2* wr = (const ulonglong2*)(w2s + h * H2V);
        #pragma unroll
        for (int i = 0; i < 8; i++) {                 // 8 x LDS.128 = 32 floats
            ulonglong2 w = wr[i];
            ffma2(acc2[2 * i],     w.x, hp);
            ffma2(acc2[2 * i + 1], w.y, hp);
        }
    }

    // bias + relu -> h2buf (reuses w1s region; all reads of w1s are long done)
    #pragma unroll
    for (int i = 0; i < 16; i++) {
        float lo, hi;
        unpack2(acc2[i], lo, hi);
        lo = fmaxf(lo + b2s[2 * i],     0.0f);
        hi = fmaxf(hi + b2s[2 * i + 1], 0.0f);
        h2buf[(2 * i)     * ROWP + t] = lo;
        h2buf[(2 * i + 1) * ROWP + t] = hi;
    }
    __syncthreads();

    // ---- BN2 stats: 8 threads per feature, 32 elements each ----
    {
        int f = t >> 3, part = t & 7;
        const float4* hv = (const float4*)(h2buf + f * ROWP + part * 32);
        float sum = 0.0f, sq = 0.0f;
        #pragma unroll
        for (int i = 0; i < 8; i++) {
            float4 v = hv[i];
            sum += v.x + v.y + v.z + v.w;
            sq  += v.x * v.x + v.y * v.y + v.z * v.z + v.w * v.w;
        }
        ps[t] = sum;
        ps[256 + t] = sq;
    }
    __syncthreads();
    if (t < H2V) {
        float sum = 0.0f, sq = 0.0f;
        #pragma unroll
        for (int i = 0; i < 8; i++) {
            sum += ps[8 * t + i];
            sq  += ps[256 + 8 * t + i];
        }
        float mean = sum * (1.0f / NB);
        float var  = sq * (1.0f / NB) - mean * mean;
        float sc   = g2[(size_t)s * H2V + t] * rsqrtf(var + EPSV);
        sc2[t] = sc;
        sh2[t] = be2[(size_t)s * H2V + t] - mean * sc;
    }
    __syncthreads();

    // ---- layer 3: out[t][s] = relu(sum_k bn2(h2[t][k]) * W3[k] + b3[s]) ----
    float acc3 = 0.0f;
    #pragma unroll
    for (int k = 0; k < H2V; k++)
        acc3 += fmaf(h2buf[k * ROWP + t], sc2[k], sh2[k]) * w3s[k];

    out[(size_t)t * NSETS + s] = fmaxf(acc3 + b3[s], 0.0f);
}

// ---------------------------------------------------------------------------
// Inputs (metadata order): x, gene_idx, W1, b1, g1, be1, W2, b2, g2, be2, W3, b3
// Output: float32 [256, 1000]
// ---------------------------------------------------------------------------
extern "C" void kernel_launch(void* const* d_in, const int* in_sizes, int n_in,
                              void* d_out, int out_size) {
    const float* x        = (const float*)d_in[0];
    const int*   gene_idx = (const int*)  d_in[1];
    const float* W1       = (const float*)d_in[2];
    const float* b1       = (const float*)d_in[3];
    const float* g1       = (const float*)d_in[4];
    const float* be1      = (const float*)d_in[5];
    const float* W2       = (const float*)d_in[6];
    const float* b2       = (const float*)d_in[7];
    const float* g2       = (const float*)d_in[8];
    const float* be2      = (const float*)d_in[9];
    const float* W3       = (const float*)d_in[10];
    const float* b3       = (const float*)d_in[11];
    float* out = (float*)d_out;

    (void)in_sizes; (void)n_in; (void)out_size;

    cudaFuncSetAttribute(geneset_kernel,
                         cudaFuncAttributeMaxDynamicSharedMemorySize, SMEM_BYTES);

    dim3 tb(32, 8);
    dim3 tg((NGENES + 31) / 32, NB / 32);
    transpose_kernel<<<tg, tb>>>(x);

    geneset_kernel<<<NSETS, 256, SMEM_BYTES>>>(gene_idx,
                                               W1, b1, g1, be1,
                                               W2, b2, g2, be2,
                                               W3, b3, out);
}

// round 15
// speedup vs baseline: 1.1622x; 1.1622x over previous
#include <cuda_runtime.h>

#define NB     256
#define NSETS  1000
#define NGENES 10000
#define GG     128
#define H1V    64
#define H2V    32
#define EPSV   1e-5f

// Scratch for transposed x: xT[gene][batch], 10000 x 256 floats = 10.24 MB
__device__ float g_xT[(size_t)NGENES * NB];

typedef unsigned long long ull;

__device__ __forceinline__ ull pack2(float lo, float hi) {
    ull r;
    asm("mov.b64 %0, {%1, %2};" : "=l"(r) : "f"(lo), "f"(hi));
    return r;
}
__device__ __forceinline__ void unpack2(ull v, float& lo, float& hi) {
    asm("mov.b64 {%0, %1}, %2;" : "=f"(lo), "=f"(hi) : "l"(v));
}
// Packed dual-fp32 FMA: d = a*b + d  (elementwise on the two 32-bit halves)
__device__ __forceinline__ void ffma2(ull& d, ull a, ull b) {
    asm("fma.rn.f32x2 %0, %1, %2, %0;" : "+l"(d) : "l"(a), "l"(b));
}

// ---------------------------------------------------------------------------
// Kernel 1: transpose x [256, 10000] -> g_xT [10000, 256]
// ---------------------------------------------------------------------------
__global__ void transpose_kernel(const float* __restrict__ x) {
    __shared__ float tile[32][33];
    int tx = threadIdx.x, ty = threadIdx.y;
    int c0 = blockIdx.x * 32;      // gene dim
    int r0 = blockIdx.y * 32;      // batch dim

    #pragma unroll
    for (int i = 0; i < 32; i += 8) {
        int c = c0 + tx;
        if (c < NGENES)
            tile[ty + i][tx] = x[(size_t)(r0 + ty + i) * NGENES + c];
    }
    __syncthreads();
    #pragma unroll
    for (int i = 0; i < 32; i += 8) {
        int gene = c0 + ty + i;
        if (gene < NGENES)
            g_xT[(size_t)gene * NB + r0 + tx] = tile[tx][ty + i];
    }
}

// ---------------------------------------------------------------------------
// Kernel 2: one CTA per set, 256 threads, register-tiled GEMMs.
//
// SMEM layout (floats), total 27584 = 110336 bytes:
//   region0 [0, 10240):  union
//     layer 1:  xs0 = 0      (16*256)      xs1 = 4096 (16*256)
//               w1c0 = 8192  (16*64)       w1c1 = 9216 (16*64)
//     layer 2+: w2s = 0 (64*32=2048)       h2buf = 2048 (32*256=8192)
//   h1buf = 10240   (64*256 = 16384)
//   misc  = 26624:
//     b1s 26624(64) sc1 26688(64) sh1 26752(64)
//     b2s 26816(32) sc2 26848(32) sh2 26880(32) w3s 26912(32)
//     ps  26944(512) idxs 27456(128 int)
// ---------------------------------------------------------------------------
#define SMEM_FLOATS 27584
#define SMEM_BYTES  (SMEM_FLOATS * 4)

__global__ __launch_bounds__(256, 2)
void geneset_kernel(const int* __restrict__ gene_idx,
                    const float* __restrict__ W1, const float* __restrict__ b1,
                    const float* __restrict__ g1, const float* __restrict__ be1,
                    const float* __restrict__ W2, const float* __restrict__ b2,
                    const float* __restrict__ g2, const float* __restrict__ be2,
                    const float* __restrict__ W3, const float* __restrict__ b3,
                    float* __restrict__ out)
{
    extern __shared__ float sm[];
    float* xs0   = sm;
    float* xs1   = sm + 4096;
    float* w1c0  = sm + 8192;
    float* w1c1  = sm + 9216;
    float* w2s   = sm;              // alias (valid after layer 1)
    float* h2buf = sm + 2048;       // alias (valid after layer 1)
    float* h1buf = sm + 10240;
    float* b1s   = sm + 26624;
    float* sc1   = sm + 26688;
    float* sh1   = sm + 26752;
    float* b2s   = sm + 26816;
    float* sc2   = sm + 26848;
    float* sh2   = sm + 26880;
    float* w3s   = sm + 26912;
    float* ps    = sm + 26944;
    int*   idxs  = (int*)(sm + 27456);

    const int s = blockIdx.x;
    const int t = threadIdx.x;
    const int n_th = t & 7;        // 8 thread-cols
    const int m_th = t >> 3;       // 32 thread-rows
    const int m0   = m_th << 3;    // this thread's 8 batch rows

    const float* W1s = W1 + (size_t)s * (GG * H1V);

    // ---- small per-set params ----
    if (t < GG)  idxs[t] = gene_idx[s * GG + t];
    if (t < H1V) b1s[t] = b1[(size_t)s * H1V + t];
    if (t < H2V) { b2s[t] = b2[(size_t)s * H2V + t]; w3s[t] = W3[(size_t)s * H2V + t]; }
    __syncthreads();

    // chunk loader: 16 genes of gathered x (16x256) + W1 rows (16x64)
    const int kl  = t >> 4;        // gene-in-chunk handled by this thread
    const int c16 = t & 15;

    auto load_chunk = [&](int c, float* xb, float* wb) {
        const float4* src = (const float4*)(g_xT + (size_t)idxs[c * 16 + kl] * NB);
        float4* dx = (float4*)(xb + kl * NB);
        #pragma unroll
        for (int j = 0; j < 4; j++) dx[c16 + 16 * j] = src[c16 + 16 * j];
        ((float4*)wb)[t] = ((const float4*)(W1s + c * (16 * H1V)))[t];
    };

    // preload chunk 0
    load_chunk(0, xs0, w1c0);
    __syncthreads();

    // ---- layer 1: z1[m][n] = sum_g x[g][m] * W1[g][n], 8m x 8n per thread ----
    ull acc[32];                   // acc[n*4 + mj], mj = m-pair
    #pragma unroll
    for (int i = 0; i < 32; i++) acc[i] = 0ull;

    #pragma unroll 1
    for (int c = 0; c < 8; c++) {
        float* xb = (c & 1) ? xs1 : xs0;
        float* wb = (c & 1) ? w1c1 : w1c0;
        if (c < 7) load_chunk(c + 1, (c & 1) ? xs0 : xs1, (c & 1) ? w1c0 : w1c1);

        #pragma unroll
        for (int kk = 0; kk < 16; kk++) {
            const float* xrow = xb + kk * NB + m0;
            float4 a0 = *(const float4*)(xrow);
            float4 a1 = *(const float4*)(xrow + 4);
            const float* wrow = wb + (kk << 6) + (n_th << 3);
            float4 bA = *(const float4*)(wrow);
            float4 bB = *(const float4*)(wrow + 4);

            ull am[4] = { pack2(a0.x, a0.y), pack2(a0.z, a0.w),
                          pack2(a1.x, a1.y), pack2(a1.z, a1.w) };
            float bf[8] = { bA.x, bA.y, bA.z, bA.w, bB.x, bB.y, bB.z, bB.w };
            #pragma unroll
            for (int n = 0; n < 8; n++) {
                ull bb = pack2(bf[n], bf[n]);
                #pragma unroll
                for (int mj = 0; mj < 4; mj++) ffma2(acc[n * 4 + mj], am[mj], bb);
            }
        }
        __syncthreads();
    }

    // epilogue: bias + relu, store h1 as [feature][batch]
    #pragma unroll
    for (int n = 0; n < 8; n++) {
        int feat = (n_th << 3) + n;
        float bv = b1s[feat];
        float v[8];
        #pragma unroll
        for (int mj = 0; mj < 4; mj++) unpack2(acc[n * 4 + mj], v[2 * mj], v[2 * mj + 1]);
        #pragma unroll
        for (int j = 0; j < 8; j++) v[j] = fmaxf(v[j] + bv, 0.0f);
        float* dst = h1buf + feat * NB + m0;
        *(float4*)(dst)     = make_float4(v[0], v[1], v[2], v[3]);
        *(float4*)(dst + 4) = make_float4(v[4], v[5], v[6], v[7]);
    }

    // region0 is now free: load W2 (overlaps with BN1 stats work)
    {
        const float4* w2g = (const float4*)(W2 + (size_t)s * (H1V * H2V));
        ((float4*)w2s)[t]       = w2g[t];
        ((float4*)w2s)[t + 256] = w2g[t + 256];
    }
    __syncthreads();

    // ---- BN1 stats: 4 threads per feature, 64 elems each ----
    {
        int f = t >> 2, part = t & 3;
        const float4* hv = (const float4*)(h1buf + f * NB + part * 64);
        float sum = 0.0f, sq = 0.0f;
        #pragma unroll
        for (int i = 0; i < 16; i++) {
            float4 v = hv[i];
            sum += v.x + v.y + v.z + v.w;
            sq  += v.x * v.x + v.y * v.y + v.z * v.z + v.w * v.w;
        }
        ps[t] = sum;
        ps[256 + t] = sq;
    }
    __syncthreads();
    if (t < H1V) {
        float sum = ps[4 * t] + ps[4 * t + 1] + ps[4 * t + 2] + ps[4 * t + 3];
        float sq  = ps[256 + 4 * t] + ps[256 + 4 * t + 1] + ps[256 + 4 * t + 2] + ps[256 + 4 * t + 3];
        float mean = sum * (1.0f / NB);
        float var  = sq * (1.0f / NB) - mean * mean;
        float sc   = g1[(size_t)s * H1V + t] * rsqrtf(var + EPSV);
        sc1[t] = sc;
        sh1[t] = be1[(size_t)s * H1V + t] - mean * sc;
    }
    __syncthreads();

    // ---- layer 2: 8m x 4n per thread. M=256, N=32, K=64 ----
    const int n2 = n_th << 2;      // features n2..n2+3
    ull acc2[16];                  // acc2[n*4 + mj]
    #pragma unroll
    for (int i = 0; i < 16; i++) acc2[i] = 0ull;

    #pragma unroll 8
    for (int k = 0; k < H1V; k++) {
        float sck = sc1[k], shk = sh1[k];
        const float* hrow = h1buf + k * NB + m0;
        float4 a0 = *(const float4*)(hrow);
        float4 a1 = *(const float4*)(hrow + 4);
        a0.x = fmaf(a0.x, sck, shk); a0.y = fmaf(a0.y, sck, shk);
        a0.z = fmaf(a0.z, sck, shk); a0.w = fmaf(a0.w, sck, shk);
        a1.x = fmaf(a1.x, sck, shk); a1.y = fmaf(a1.y, sck, shk);
        a1.z = fmaf(a1.z, sck, shk); a1.w = fmaf(a1.w, sck, shk);
        float4 bv = *(const float4*)(w2s + (k << 5) + n2);

        ull am[4] = { pack2(a0.x, a0.y), pack2(a0.z, a0.w),
                      pack2(a1.x, a1.y), pack2(a1.z, a1.w) };
        float bf[4] = { bv.x, bv.y, bv.z, bv.w };
        #pragma unroll
        for (int n = 0; n < 4; n++) {
            ull bb = pack2(bf[n], bf[n]);
            #pragma unroll
            for (int mj = 0; mj < 4; mj++) ffma2(acc2[n * 4 + mj], am[mj], bb);
        }
    }

    // epilogue: bias + relu, store h2 as [feature][batch]
    #pragma unroll
    for (int n = 0; n < 4; n++) {
        int feat = n2 + n;
        float bv = b2s[feat];
        float v[8];
        #pragma unroll
        for (int mj = 0; mj < 4; mj++) unpack2(acc2[n * 4 + mj], v[2 * mj], v[2 * mj + 1]);
        #pragma unroll
        for (int j = 0; j < 8; j++) v[j] = fmaxf(v[j] + bv, 0.0f);
        float* dst = h2buf + feat * NB + m0;
        *(float4*)(dst)     = make_float4(v[0], v[1], v[2], v[3]);
        *(float4*)(dst + 4) = make_float4(v[4], v[5], v[6], v[7]);
    }
    __syncthreads();

    // ---- BN2 stats: 8 threads per feature, 32 elems each ----
    {
        int f = t >> 3, part = t & 7;
        const float4* hv = (const float4*)(h2buf + f * NB + part * 32);
        float sum = 0.0f, sq = 0.0f;
        #pragma unroll
        for (int i = 0; i < 8; i++) {
            float4 v = hv[i];
            sum += v.x + v.y + v.z + v.w;
            sq  += v.x * v.x + v.y * v.y + v.z * v.z + v.w * v.w;
        }
        ps[t] = sum;
        ps[256 + t] = sq;
    }
    __syncthreads();
    if (t < H2V) {
        float sum = 0.0f, sq = 0.0f;
        #pragma unroll
        for (int i = 0; i < 8; i++) {
            sum += ps[8 * t + i];
            sq  += ps[256 + 8 * t + i];
        }
        float mean = sum * (1.0f / NB);
        float var  = sq * (1.0f / NB) - mean * mean;
        float sc   = g2[(size_t)s * H2V + t] * rsqrtf(var + EPSV);
        sc2[t] = sc;
        sh2[t] = be2[(size_t)s * H2V + t] - mean * sc;
    }
    __syncthreads();

    // ---- layer 3: out[t][s] = relu(sum_k bn2(h2[k][t]) * W3[k] + b3[s]) ----
    float acc3 = 0.0f;
    #pragma unroll
    for (int k = 0; k < H2V; k++)
        acc3 += fmaf(h2buf[k * NB + t], sc2[k], sh2[k]) * w3s[k];

    out[(size_t)t * NSETS + s] = fmaxf(acc3 + b3[s], 0.0f);
}

// ---------------------------------------------------------------------------
// Inputs: x, gene_idx, W1, b1, g1, be1, W2, b2, g2, be2, W3, b3
// Output: float32 [256, 1000]
// ---------------------------------------------------------------------------
extern "C" void kernel_launch(void* const* d_in, const int* in_sizes, int n_in,
                              void* d_out, int out_size) {
    const float* x        = (const float*)d_in[0];
    const int*   gene_idx = (const int*)  d_in[1];
    const float* W1       = (const float*)d_in[2];
    const float* b1       = (const float*)d_in[3];
    const float* g1       = (const float*)d_in[4];
    const float* be1      = (const float*)d_in[5];
    const float* W2       = (const float*)d_in[6];
    const float* b2       = (const float*)d_in[7];
    const float* g2       = (const float*)d_in[8];
    const float* be2      = (const float*)d_in[9];
    const float* W3       = (const float*)d_in[10];
    const float* b3       = (const float*)d_in[11];
    float* out = (float*)d_out;

    (void)in_sizes; (void)n_in; (void)out_size;

    cudaFuncSetAttribute(geneset_kernel,
                         cudaFuncAttributeMaxDynamicSharedMemorySize, SMEM_BYTES);

    dim3 tb(32, 8);
    dim3 tg((NGENES + 31) / 32, NB / 32);
    transpose_kernel<<<tg, tb>>>(x);

    geneset_kernel<<<NSETS, 256, SMEM_BYTES>>>(gene_idx,
                                               W1, b1, g1, be1,
                                               W2, b2, g2, be2,
                                               W3, b3, out);
}

// round 16
// speedup vs baseline: 1.1636x; 1.0012x over previous
#include <cuda_runtime.h>

#define NB     256
#define NSETS  1000
#define NGENES 10000
#define GG     128
#define H1V    64
#define H2V    32
#define EPSV   1e-5f

// Scratch for transposed x: xT[gene][batch], 10000 x 256 floats = 10.24 MB
__device__ float g_xT[(size_t)NGENES * NB];

typedef unsigned long long ull;

__device__ __forceinline__ ull pack2(float lo, float hi) {
    ull r;
    asm("mov.b64 %0, {%1, %2};" : "=l"(r) : "f"(lo), "f"(hi));
    return r;
}
__device__ __forceinline__ void unpack2(ull v, float& lo, float& hi) {
    asm("mov.b64 {%0, %1}, %2;" : "=f"(lo), "=f"(hi) : "l"(v));
}
// Packed dual-fp32 FMA: d = a*b + d  (elementwise on the two 32-bit halves)
__device__ __forceinline__ void ffma2(ull& d, ull a, ull b) {
    asm("fma.rn.f32x2 %0, %1, %2, %0;" : "+l"(d) : "l"(a), "l"(b));
}

// ---------------------------------------------------------------------------
// Kernel 1: transpose x [256, 10000] -> g_xT [10000, 256]
// ---------------------------------------------------------------------------
__global__ void transpose_kernel(const float* __restrict__ x) {
    __shared__ float tile[32][33];
    int tx = threadIdx.x, ty = threadIdx.y;
    int c0 = blockIdx.x * 32;      // gene dim
    int r0 = blockIdx.y * 32;      // batch dim

    #pragma unroll
    for (int i = 0; i < 32; i += 8) {
        int c = c0 + tx;
        if (c < NGENES)
            tile[ty + i][tx] = x[(size_t)(r0 + ty + i) * NGENES + c];
    }
    __syncthreads();
    #pragma unroll
    for (int i = 0; i < 32; i += 8) {
        int gene = c0 + ty + i;
        if (gene < NGENES)
            g_xT[(size_t)gene * NB + r0 + tx] = tile[tx][ty + i];
    }
}

// ---------------------------------------------------------------------------
// Kernel 2: one CTA per set, 256 threads, register-tiled GEMMs.
//
// SMEM layout (floats), total 27584 = 110336 bytes:
//   region0 [0, 10240):  union
//     layer 1:  xs0 = 0      (16*256)      xs1 = 4096 (16*256)
//               w1c0 = 8192  (16*64)       w1c1 = 9216 (16*64)
//     layer 2+: w2s = 0 (64*32=2048)       h2buf = 2048 (32*256=8192)
//   h1buf = 10240   (64*256 = 16384)
//   misc  = 26624:
//     b1s 26624(64) sc1 26688(64) sh1 26752(64)
//     b2s 26816(32) sc2 26848(32) sh2 26880(32) w3s 26912(32)
//     ps  26944(512) idxs 27456(128 int)
// ---------------------------------------------------------------------------
#define SMEM_FLOATS 27584
#define SMEM_BYTES  (SMEM_FLOATS * 4)

__global__ __launch_bounds__(256, 2)
void geneset_kernel(const int* __restrict__ gene_idx,
                    const float* __restrict__ W1, const float* __restrict__ b1,
                    const float* __restrict__ g1, const float* __restrict__ be1,
                    const float* __restrict__ W2, const float* __restrict__ b2,
                    const float* __restrict__ g2, const float* __restrict__ be2,
                    const float* __restrict__ W3, const float* __restrict__ b3,
                    float* __restrict__ out)
{
    extern __shared__ float sm[];
    float* xs0   = sm;
    float* xs1   = sm + 4096;
    float* w1c0  = sm + 8192;
    float* w1c1  = sm + 9216;
    float* w2s   = sm;              // alias (valid after layer 1)
    float* h2buf = sm + 2048;       // alias (valid after layer 1)
    float* h1buf = sm + 10240;
    float* b1s   = sm + 26624;
    float* sc1   = sm + 26688;
    float* sh1   = sm + 26752;
    float* b2s   = sm + 26816;
    float* sc2   = sm + 26848;
    float* sh2   = sm + 26880;
    float* w3s   = sm + 26912;
    float* ps    = sm + 26944;
    int*   idxs  = (int*)(sm + 27456);

    const int s = blockIdx.x;
    const int t = threadIdx.x;
    const int n_th = t & 7;        // 8 thread-cols
    const int m_th = t >> 3;       // 32 thread-rows
    const int m0   = m_th << 3;    // this thread's 8 batch rows

    const float* W1s = W1 + (size_t)s * (GG * H1V);

    // ---- small per-set params ----
    if (t < GG)  idxs[t] = gene_idx[s * GG + t];
    if (t < H1V) b1s[t] = b1[(size_t)s * H1V + t];
    if (t < H2V) { b2s[t] = b2[(size_t)s * H2V + t]; w3s[t] = W3[(size_t)s * H2V + t]; }
    __syncthreads();

    // chunk loader: 16 genes of gathered x (16x256) + W1 rows (16x64)
    const int kl  = t >> 4;        // gene-in-chunk handled by this thread
    const int c16 = t & 15;

    auto load_chunk = [&](int c, float* xb, float* wb) {
        const float4* src = (const float4*)(g_xT + (size_t)idxs[c * 16 + kl] * NB);
        float4* dx = (float4*)(xb + kl * NB);
        #pragma unroll
        for (int j = 0; j < 4; j++) dx[c16 + 16 * j] = src[c16 + 16 * j];
        ((float4*)wb)[t] = ((const float4*)(W1s + c * (16 * H1V)))[t];
    };

    // preload chunk 0
    load_chunk(0, xs0, w1c0);
    __syncthreads();

    // ---- layer 1: z1[m][n] = sum_g x[g][m] * W1[g][n], 8m x 8n per thread ----
    ull acc[32];                   // acc[n*4 + mj], mj = m-pair
    #pragma unroll
    for (int i = 0; i < 32; i++) acc[i] = 0ull;

    #pragma unroll 1
    for (int c = 0; c < 8; c++) {
        float* xb = (c & 1) ? xs1 : xs0;
        float* wb = (c & 1) ? w1c1 : w1c0;
        if (c < 7) load_chunk(c + 1, (c & 1) ? xs0 : xs1, (c & 1) ? w1c0 : w1c1);

        #pragma unroll
        for (int kk = 0; kk < 16; kk++) {
            const float* xrow = xb + kk * NB + m0;
            float4 a0 = *(const float4*)(xrow);
            float4 a1 = *(const float4*)(xrow + 4);
            const float* wrow = wb + (kk << 6) + (n_th << 3);
            float4 bA = *(const float4*)(wrow);
            float4 bB = *(const float4*)(wrow + 4);

            ull am[4] = { pack2(a0.x, a0.y), pack2(a0.z, a0.w),
                          pack2(a1.x, a1.y), pack2(a1.z, a1.w) };
            float bf[8] = { bA.x, bA.y, bA.z, bA.w, bB.x, bB.y, bB.z, bB.w };
            #pragma unroll
            for (int n = 0; n < 8; n++) {
                ull bb = pack2(bf[n], bf[n]);
                #pragma unroll
                for (int mj = 0; mj < 4; mj++) ffma2(acc[n * 4 + mj], am[mj], bb);
            }
        }
        __syncthreads();
    }

    // epilogue: bias + relu, store h1 as [feature][batch]
    #pragma unroll
    for (int n = 0; n < 8; n++) {
        int feat = (n_th << 3) + n;
        float bv = b1s[feat];
        float v[8];
        #pragma unroll
        for (int mj = 0; mj < 4; mj++) unpack2(acc[n * 4 + mj], v[2 * mj], v[2 * mj + 1]);
        #pragma unroll
        for (int j = 0; j < 8; j++) v[j] = fmaxf(v[j] + bv, 0.0f);
        float* dst = h1buf + feat * NB + m0;
        *(float4*)(dst)     = make_float4(v[0], v[1], v[2], v[3]);
        *(float4*)(dst + 4) = make_float4(v[4], v[5], v[6], v[7]);
    }

    // region0 is now free: load W2 (overlaps with BN1 stats work)
    {
        const float4* w2g = (const float4*)(W2 + (size_t)s * (H1V * H2V));
        ((float4*)w2s)[t]       = w2g[t];
        ((float4*)w2s)[t + 256] = w2g[t + 256];
    }
    __syncthreads();

    // ---- BN1 stats: 4 threads per feature, 64 elems each ----
    {
        int f = t >> 2, part = t & 3;
        const float4* hv = (const float4*)(h1buf + f * NB + part * 64);
        float sum = 0.0f, sq = 0.0f;
        #pragma unroll
        for (int i = 0; i < 16; i++) {
            float4 v = hv[i];
            sum += v.x + v.y + v.z + v.w;
            sq  += v.x * v.x + v.y * v.y + v.z * v.z + v.w * v.w;
        }
        ps[t] = sum;
        ps[256 + t] = sq;
    }
    __syncthreads();
    if (t < H1V) {
        float sum = ps[4 * t] + ps[4 * t + 1] + ps[4 * t + 2] + ps[4 * t + 3];
        float sq  = ps[256 + 4 * t] + ps[256 + 4 * t + 1] + ps[256 + 4 * t + 2] + ps[256 + 4 * t + 3];
        float mean = sum * (1.0f / NB);
        float var  = sq * (1.0f / NB) - mean * mean;
        float sc   = g1[(size_t)s * H1V + t] * rsqrtf(var + EPSV);
        sc1[t] = sc;
        sh1[t] = be1[(size_t)s * H1V + t] - mean * sc;
    }
    __syncthreads();

    // ---- layer 2: 8m x 4n per thread. M=256, N=32, K=64 ----
    const int n2 = n_th << 2;      // features n2..n2+3
    ull acc2[16];                  // acc2[n*4 + mj]
    #pragma unroll
    for (int i = 0; i < 16; i++) acc2[i] = 0ull;

    #pragma unroll 8
    for (int k = 0; k < H1V; k++) {
        float sck = sc1[k], shk = sh1[k];
        const float* hrow = h1buf + k * NB + m0;
        float4 a0 = *(const float4*)(hrow);
        float4 a1 = *(const float4*)(hrow + 4);
        a0.x = fmaf(a0.x, sck, shk); a0.y = fmaf(a0.y, sck, shk);
        a0.z = fmaf(a0.z, sck, shk); a0.w = fmaf(a0.w, sck, shk);
        a1.x = fmaf(a1.x, sck, shk); a1.y = fmaf(a1.y, sck, shk);
        a1.z = fmaf(a1.z, sck, shk); a1.w = fmaf(a1.w, sck, shk);
        float4 bv = *(const float4*)(w2s + (k << 5) + n2);

        ull am[4] = { pack2(a0.x, a0.y), pack2(a0.z, a0.w),
                      pack2(a1.x, a1.y), pack2(a1.z, a1.w) };
        float bf[4] = { bv.x, bv.y, bv.z, bv.w };
        #pragma unroll
        for (int n = 0; n < 4; n++) {
            ull bb = pack2(bf[n], bf[n]);
            #pragma unroll
            for (int mj = 0; mj < 4; mj++) ffma2(acc2[n * 4 + mj], am[mj], bb);
        }
    }

    // epilogue: bias + relu, store h2 as [feature][batch]
    #pragma unroll
    for (int n = 0; n < 4; n++) {
        int feat = n2 + n;
        float bv = b2s[feat];
        float v[8];
        #pragma unroll
        for (int mj = 0; mj < 4; mj++) unpack2(acc2[n * 4 + mj], v[2 * mj], v[2 * mj + 1]);
        #pragma unroll
        for (int j = 0; j < 8; j++) v[j] = fmaxf(v[j] + bv, 0.0f);
        float* dst = h2buf + feat * NB + m0;
        *(float4*)(dst)     = make_float4(v[0], v[1], v[2], v[3]);
        *(float4*)(dst + 4) = make_float4(v[4], v[5], v[6], v[7]);
    }
    __syncthreads();

    // ---- BN2 stats: 8 threads per feature, 32 elems each ----
    {
        int f = t >> 3, part = t & 7;
        const float4* hv = (const float4*)(h2buf + f * NB + part * 32);
        float sum = 0.0f, sq = 0.0f;
        #pragma unroll
        for (int i = 0; i < 8; i++) {
            float4 v = hv[i];
            sum += v.x + v.y + v.z + v.w;
            sq  += v.x * v.x + v.y * v.y + v.z * v.z + v.w * v.w;
        }
        ps[t] = sum;
        ps[256 + t] = sq;
    }
    __syncthreads();
    if (t < H2V) {
        float sum = 0.0f, sq = 0.0f;
        #pragma unroll
        for (int i = 0; i < 8; i++) {
            sum += ps[8 * t + i];
            sq  += ps[256 + 8 * t + i];
        }
        float mean = sum * (1.0f / NB);
        float var  = sq * (1.0f / NB) - mean * mean;
        float sc   = g2[(size_t)s * H2V + t] * rsqrtf(var + EPSV);
        sc2[t] = sc;
        sh2[t] = be2[(size_t)s * H2V + t] - mean * sc;
    }
    __syncthreads();

    // ---- layer 3: out[t][s] = relu(sum_k bn2(h2[k][t]) * W3[k] + b3[s]) ----
    float acc3 = 0.0f;
    #pragma unroll
    for (int k = 0; k < H2V; k++)
        acc3 += fmaf(h2buf[k * NB + t], sc2[k], sh2[k]) * w3s[k];

    out[(size_t)t * NSETS + s] = fmaxf(acc3 + b3[s], 0.0f);
}

// ---------------------------------------------------------------------------
// Inputs: x, gene_idx, W1, b1, g1, be1, W2, b2, g2, be2, W3, b3
// Output: float32 [256, 1000]
// ---------------------------------------------------------------------------
extern "C" void kernel_launch(void* const* d_in, const int* in_sizes, int n_in,
                              void* d_out, int out_size) {
    const float* x        = (const float*)d_in[0];
    const int*   gene_idx = (const int*)  d_in[1];
    const float* W1       = (const float*)d_in[2];
    const float* b1       = (const float*)d_in[3];
    const float* g1       = (const float*)d_in[4];
    const float* be1      = (const float*)d_in[5];
    const float* W2       = (const float*)d_in[6];
    const float* b2       = (const float*)d_in[7];
    const float* g2       = (const float*)d_in[8];
    const float* be2      = (const float*)d_in[9];
    const float* W3       = (const float*)d_in[10];
    const float* b3       = (const float*)d_in[11];
    float* out = (float*)d_out;

    (void)in_sizes; (void)n_in; (void)out_size;

    cudaFuncSetAttribute(geneset_kernel,
                         cudaFuncAttributeMaxDynamicSharedMemorySize, SMEM_BYTES);

    dim3 tb(32, 8);
    dim3 tg((NGENES + 31) / 32, NB / 32);
    transpose_kernel<<<tg, tb>>>(x);

    geneset_kernel<<<NSETS, 256, SMEM_BYTES>>>(gene_idx,
                                               W1, b1, g1, be1,
                                               W2, b2, g2, be2,
                                               W3, b3, out);
}